// round 16
// baseline (speedup 1.0000x reference)
#include <cuda_runtime.h>
#include <cuda_fp16.h>
#include <math.h>
#include <cstdint>

#define S_LEN 4096
#define HID   2048
#define NH    8
#define HD    256
#define NQKV  2560      // 2048 (Q) + 256 (K) + 256 (V)

typedef unsigned short u16;

// ------------------------- device scratch (no allocs allowed) ---------------
__device__ float g_QKV[(size_t)S_LEN * NQKV];        // 40 MB fp32 proj out

__device__ u16 g_Xh  [(size_t)S_LEN * HID];          // fp16 single planes
__device__ u16 g_Qh  [(size_t)S_LEN * HID];
__device__ u16 g_P   [(size_t)NH * S_LEN * S_LEN];   // 268 MB fp16 scores -> P in place
__device__ u16 g_Ah  [(size_t)S_LEN * HID];
__device__ u16 g_Kh  [(size_t)S_LEN * HD];
__device__ u16 g_VTh [(size_t)HD * S_LEN];
__device__ u16 g_Wh  [(size_t)NQKV * HID];           // concat Wq|Wk|Wv transposed, x64
__device__ u16 g_WoTh[(size_t)HID * HID];            // Wo transposed, x64

// ------------------------- helpers ------------------------------------------
__device__ __forceinline__ u16 to_h(float x) {
    return __half_as_ushort(__float2half_rn(x));
}
__device__ __forceinline__ uint32_t smem_u32(const void* p) {
    uint32_t a;
    asm("{ .reg .u64 t; cvta.to.shared.u64 t, %1; cvt.u32.u64 %0, t; }"
        : "=r"(a) : "l"(p));
    return a;
}
__device__ __forceinline__ void cpa16(uint32_t dst, const void* src) {
    asm volatile("cp.async.cg.shared.global [%0], [%1], 16;" :: "r"(dst), "l"(src));
}
__device__ __forceinline__ void cpa_commit() {
    asm volatile("cp.async.commit_group;");
}

#define LDSM4(r, a)                                                            \
    asm volatile("ldmatrix.sync.aligned.m8n8.x4.shared.b16 {%0,%1,%2,%3}, [%4];" \
        : "=r"((r)[0]), "=r"((r)[1]), "=r"((r)[2]), "=r"((r)[3]) : "r"(a))

#define MMA_F16(acc, a, b)                                                     \
    asm volatile(                                                              \
        "mma.sync.aligned.m16n8k16.row.col.f32.f16.f16.f32 "                   \
        "{%0,%1,%2,%3},{%4,%5,%6,%7},{%8,%9},{%0,%1,%2,%3};"                   \
        : "+f"((acc)[0]), "+f"((acc)[1]), "+f"((acc)[2]), "+f"((acc)[3])       \
        : "r"((a)[0]), "r"((a)[1]), "r"((a)[2]), "r"((a)[3]),                  \
          "r"((b)[0]), "r"((b)[1]))

// epilogue store overloads
__device__ __forceinline__ void store2(float* C, long long idx, float a, float b) {
    *(float2*)(C + idx) = make_float2(a, b);
}
__device__ __forceinline__ void store2(u16* C, long long idx, float a, float b) {
    *(__half2*)(C + idx) = __floats2half2_rn(a, b);
}

// ---------------------------------------------------------------------------
// fp16 single-pass GEMM (NT): C[m,n] = alpha * sum_k A[m,k]*B[n,k]
// CTA tile 256x128, 256 threads / 8 warps in 4x2 grid of 64x64 warp tiles.
// 1 CTA/SM; K-chunk 64; 4 SMEM buffers (192 KB), 3 in-flight cp.async groups,
// one __syncthreads per chunk.
// Crossbar per chunk: A 32KB*2 + B 16KB*4 + STS 48KB = 176KB (1408 cyc)
// vs 4096 MMA cycles -> tensor-pipe bound, crossbar at 34%.
// SMEM rows: 64 u16 = 128 B, swizzle g' = g ^ (row & 7).
// M multiple of 256, N of 128, K of 64.
// ---------------------------------------------------------------------------
#define PLANEA_B (256 * 128)            // 32768 B  A tile
#define PLANEB_B (128 * 128)            // 16384 B  B tile
#define STAGE_B  (PLANEA_B + PLANEB_B)  // 49152 B
#define NSTAGE   4
#define GEMM_SMEM (NSTAGE * STAGE_B)    // 196608 B

template <typename OT>
__global__ void __launch_bounds__(256, 1) bgemm(
    const u16* __restrict__ A, const u16* __restrict__ B,
    OT* __restrict__ C,
    int K, int lda, int ldb, int ldc,
    long long sA, long long sB, long long sC, float alpha)
{
    extern __shared__ u16 smraw[];
    const uint32_t smb = smem_u32(smraw);

    const int tid  = threadIdx.x;
    const int wid  = tid >> 5;
    const int lane = tid & 31;
    const int g    = lane >> 2;
    const int tg   = lane & 3;
    const int wm   = (wid >> 1) * 64;   // 4x2 warp grid over 256x128
    const int wn   = (wid & 1) * 64;

    const int z  = blockIdx.z;
    const int m0 = blockIdx.y * 256;
    const int n0 = blockIdx.x * 128;
    const u16* gA = A + (long long)z * sA + (long long)m0 * lda;
    const u16* gB = B + (long long)z * sB + (long long)n0 * ldb;
    C += (long long)z * sC;

    const int gi    = tid & 7;          // 16B granule within 128B row
    const int rbase = tid >> 3;         // 0..31

    auto issue = [&](int c) {
        const uint32_t sbase = smb + (uint32_t)(c & (NSTAGE - 1)) * STAGE_B;
        const int k0 = c << 6;
#pragma unroll
        for (int t = 0; t < 12; t++) {
            const bool isA = (t < 8);
            const int row  = ((isA ? t : (t - 8)) << 5) + rbase;  // A:0..255 B:0..127
            const int gs   = gi ^ (row & 7);
            const u16* src = isA ? gA : gB;
            const int ld   = isA ? lda : ldb;
            const uint32_t po = isA ? 0u : (uint32_t)PLANEA_B;
            cpa16(sbase + po + (uint32_t)(row * 128 + (gs << 4)),
                  src + (long long)row * ld + k0 + gi * 8);
        }
        cpa_commit();
    };

    float acc[4][8][4];
#pragma unroll
    for (int i = 0; i < 4; i++)
#pragma unroll
        for (int j = 0; j < 8; j++)
#pragma unroll
            for (int r = 0; r < 4; r++) acc[i][j][r] = 0.0f;

    // per-lane ldmatrix base offsets; full offset = base ^ (ks << 5)
    const int l8 = lane & 7;
    const int lt = lane >> 3;
    const int rA = ((lt & 1) << 3) + l8;
    const int gA4 = lt >> 1;
    const int rB = ((lt >> 1) << 3) + l8;
    const int gB4 = lt & 1;

    uint32_t baseA[4], baseB[4];
#pragma unroll
    for (int tm = 0; tm < 4; tm++) {
        const int R = wm + tm * 16 + rA;
        const int s = R & 7;
        baseA[tm] = (uint32_t)(R * 128 + ((gA4 ^ (s & 1)) << 4) + ((s & 6) << 4));
    }
#pragma unroll
    for (int j = 0; j < 4; j++) {
        const int R = wn + j * 16 + rB;
        const int s = R & 7;
        baseB[j] = (uint32_t)(R * 128 + ((gB4 ^ (s & 1)) << 4) + ((s & 6) << 4));
    }

    const int nc = K >> 6;
    issue(0);
    if (nc > 1) issue(1);
    if (nc > 2) issue(2);

    for (int c = 0; c < nc; c++) {
        const int rem = nc - 1 - c;
        if (rem >= 2)      asm volatile("cp.async.wait_group 2;");
        else if (rem == 1) asm volatile("cp.async.wait_group 1;");
        else               asm volatile("cp.async.wait_group 0;");
        __syncthreads();
        if (c + 3 < nc) issue(c + 3);

        const uint32_t st  = smb + (uint32_t)(c & (NSTAGE - 1)) * STAGE_B;
        const uint32_t aPl = st;
        const uint32_t bPl = st + PLANEA_B;

#pragma unroll
        for (int ks = 0; ks < 4; ks++) {
            const uint32_t kx = (uint32_t)(ks << 5);
            uint32_t a[4][4], b[8][2];
            LDSM4(a[0], aPl + (baseA[0] ^ kx));
            LDSM4(a[1], aPl + (baseA[1] ^ kx));
            LDSM4(a[2], aPl + (baseA[2] ^ kx));
            LDSM4(a[3], aPl + (baseA[3] ^ kx));
#pragma unroll
            for (int j = 0; j < 4; j++) {
                uint32_t r[4];
                LDSM4(r, bPl + (baseB[j] ^ kx));
                b[2 * j][0] = r[0]; b[2 * j][1] = r[1];
                b[2 * j + 1][0] = r[2]; b[2 * j + 1][1] = r[3];
            }
#pragma unroll
            for (int tm = 0; tm < 4; tm++)
#pragma unroll
                for (int tn = 0; tn < 8; tn++) MMA_F16(acc[tm][tn], a[tm], b[tn]);
        }
    }

    // epilogue
#pragma unroll
    for (int tm = 0; tm < 4; tm++) {
        const int row = m0 + wm + tm * 16 + g;
#pragma unroll
        for (int tn = 0; tn < 8; tn++) {
            const int col = n0 + wn + tn * 8 + 2 * tg;
            store2(C, (long long)row * ldc + col,
                   acc[tm][tn][0] * alpha, acc[tm][tn][1] * alpha);
            store2(C, (long long)(row + 8) * ldc + col,
                   acc[tm][tn][2] * alpha, acc[tm][tn][3] * alpha);
        }
    }
}

// ---------------------------------------------------------------------------
// fp32 -> fp16 single-plane pack
// ---------------------------------------------------------------------------
__global__ void __launch_bounds__(256) pack_half_kernel(
    const float* __restrict__ in, u16* __restrict__ out, long long n4)
{
    const long long i = (long long)blockIdx.x * 256 + threadIdx.x;
    if (i >= n4) return;
    const float4 v = ((const float4*)in)[i];
    ushort4 o;
    o.x = to_h(v.x); o.y = to_h(v.y); o.z = to_h(v.z); o.w = to_h(v.w);
    ((ushort4*)out)[i] = o;
}

// ---------------------------------------------------------------------------
// Weight transpose + x64 scale -> single fp16 plane.
// ---------------------------------------------------------------------------
__global__ void __launch_bounds__(256) transpose_weights_kernel(
    const float* __restrict__ Wq, const float* __restrict__ Wk,
    const float* __restrict__ Wv, const float* __restrict__ Wo)
{
    __shared__ float tile[32][33];
    const int b = blockIdx.x;
    const int x = threadIdx.x;
    const int y = threadIdx.y;

    const float* src; int scol, sC, n0, k0;
    u16* oh;
    if (b < 5120) {
        const int bx = b % 80, by = b / 80;
        n0 = bx * 32; k0 = by * 32;
        if (n0 < 2048)      { src = Wq; scol = n0;        sC = 2048; }
        else if (n0 < 2304) { src = Wk; scol = n0 - 2048; sC = 256; }
        else                { src = Wv; scol = n0 - 2304; sC = 256; }
        oh = g_Wh;
    } else {
        const int bb = b - 5120;
        const int bx = bb % 64, by = bb / 64;
        n0 = bx * 32; k0 = by * 32;
        src = Wo; scol = n0; sC = 2048;
        oh = g_WoTh;
    }
#pragma unroll
    for (int i = 0; i < 32; i += 8)
        tile[y + i][x] = src[(long long)(k0 + y + i) * sC + scol + x];
    __syncthreads();
#pragma unroll
    for (int i = 0; i < 32; i += 8)
        oh[(long long)(n0 + y + i) * HID + k0 + x] = to_h(tile[x][y + i] * 64.0f);
}

// ---------------------------------------------------------------------------
// RoPE: g_QKV -> Qh, Kh single fp16 planes
// ---------------------------------------------------------------------------
__global__ void rope_kernel(const int* __restrict__ pos_ids)
{
    const int s = blockIdx.x;
    const int j = threadIdx.x;           // 0..127
    const float p = (float)pos_ids[s];
    const float inv = expf(-((float)j * (1.0f / 128.0f)) * logf(10000.0f));
    const float ang = p * inv;
    const float c  = cosf(ang);
    const float sn = sinf(ang);

    const float* row = g_QKV + (size_t)s * NQKV;
#pragma unroll
    for (int h = 0; h < NH; h++) {
        const float x1 = row[h * HD + j];
        const float x2 = row[h * HD + j + 128];
        const size_t o = (size_t)s * HID + h * HD;
        g_Qh[o + j]       = to_h(x1 * c - x2 * sn);
        g_Qh[o + j + 128] = to_h(x2 * c + x1 * sn);
    }
    {
        const float x1 = row[2048 + j];
        const float x2 = row[2048 + j + 128];
        const size_t o = (size_t)s * HD;
        g_Kh[o + j]       = to_h(x1 * c - x2 * sn);
        g_Kh[o + j + 128] = to_h(x2 * c + x1 * sn);
    }
}

// ---------------------------------------------------------------------------
// V transpose: g_QKV cols [2304,2560) -> VT single fp16 plane [256, 4096]
// ---------------------------------------------------------------------------
__global__ void __launch_bounds__(256) transpose_v_kernel()
{
    __shared__ float tile[32][33];
    const int c0 = blockIdx.x * 32;    // d
    const int r0 = blockIdx.y * 32;    // s
    const int x = threadIdx.x;
    const int y = threadIdx.y;
#pragma unroll
    for (int i = 0; i < 32; i += 8)
        tile[y + i][x] = g_QKV[(size_t)(r0 + y + i) * NQKV + 2304 + c0 + x];
    __syncthreads();
#pragma unroll
    for (int i = 0; i < 32; i += 8)
        g_VTh[(size_t)(c0 + y + i) * S_LEN + r0 + x] = to_h(tile[x][y + i]);
}

// ---------------------------------------------------------------------------
// Softmax in-place on fp16 scores (g_P): one block per q row, all 8 heads.
// Vectorized contiguous loads; warp-shuffle reductions.
// ---------------------------------------------------------------------------
__device__ __forceinline__ float block_reduce(float x, float* red, int tid, bool ismax)
{
#pragma unroll
    for (int o = 16; o > 0; o >>= 1) {
        const float y = __shfl_xor_sync(0xFFFFFFFFu, x, o);
        x = ismax ? fmaxf(x, y) : (x + y);
    }
    if ((tid & 31) == 0) red[tid >> 5] = x;
    __syncthreads();
    if (tid < 8) {
        float y = red[tid];
#pragma unroll
        for (int o = 4; o > 0; o >>= 1) {
            const float z = __shfl_xor_sync(0xFFu, y, o);
            y = ismax ? fmaxf(y, z) : (y + z);
        }
        red[tid] = y;
    }
    __syncthreads();
    const float r = red[0];
    __syncthreads();   // allow red reuse
    return r;
}

__global__ void __launch_bounds__(256) softmax_kernel(const float* __restrict__ mask)
{
    const int q = blockIdx.x;
    const int tid = threadIdx.x;
    __shared__ float msk[S_LEN];
    __shared__ float red[8];

    {
        const float4* m4 = (const float4*)(mask + (size_t)q * S_LEN);
        float4* s4 = (float4*)msk;
#pragma unroll
        for (int i = 0; i < 4; i++)
            s4[tid + i * 256] = m4[tid + i * 256];
    }
    __syncthreads();

    const int col0 = tid * 16;
    for (int h = 0; h < NH; h++) {
        u16* __restrict__ row = g_P + ((size_t)h * S_LEN + q) * S_LEN;

        float v[16];
        {
            const uint4 w0 = *(const uint4*)(row + col0);
            const uint4 w1 = *(const uint4*)(row + col0 + 8);
            const uint32_t ws[8] = {w0.x, w0.y, w0.z, w0.w, w1.x, w1.y, w1.z, w1.w};
#pragma unroll
            for (int i = 0; i < 8; i++) {
                const float2 f = __half22float2(*(const __half2*)&ws[i]);
                v[2 * i]     = f.x + msk[col0 + 2 * i];
                v[2 * i + 1] = f.y + msk[col0 + 2 * i + 1];
            }
        }
        float m = v[0];
#pragma unroll
        for (int i = 1; i < 16; i++) m = fmaxf(m, v[i]);
        m = block_reduce(m, red, tid, true);

        float sum = 0.0f;
#pragma unroll
        for (int i = 0; i < 16; i++) {
            v[i] = __expf(v[i] - m);
            sum += v[i];
        }
        sum = block_reduce(sum, red, tid, false);
        const float inv = 1.0f / sum;

        uint4 o0, o1;
#pragma unroll
        for (int i = 0; i < 8; i++) {
            const __half2 hh = __floats2half2_rn(v[2 * i] * inv, v[2 * i + 1] * inv);
            if (i < 4) ((uint32_t*)&o0)[i] = *(const uint32_t*)&hh;
            else       ((uint32_t*)&o1)[i - 4] = *(const uint32_t*)&hh;
        }
        *(uint4*)(row + col0)     = o0;
        *(uint4*)(row + col0 + 8) = o1;
    }
}

// ---------------------------------------------------------------------------
// Launch.  #4 (ncu capture slot) = merged QKV projection GEMM.
// ---------------------------------------------------------------------------
extern "C" void kernel_launch(void* const* d_in, const int* in_sizes, int n_in,
                              void* d_out, int out_size)
{
    const float* X    = (const float*)d_in[0];
    const float* mask = (const float*)d_in[1];
    const int*   pos  = (const int*)d_in[2];
    const float* Wq   = (const float*)d_in[3];
    const float* Wk   = (const float*)d_in[4];
    const float* Wv   = (const float*)d_in[5];
    const float* Wo   = (const float*)d_in[6];
    float* out = (float*)d_out;

    float* QKV;
    u16 *Xh, *Qh, *Kh, *VTh, *P, *Ah, *Wh, *WoTh;
    cudaGetSymbolAddress((void**)&QKV,  g_QKV);
    cudaGetSymbolAddress((void**)&Xh,   g_Xh);
    cudaGetSymbolAddress((void**)&Qh,   g_Qh);
    cudaGetSymbolAddress((void**)&Kh,   g_Kh);
    cudaGetSymbolAddress((void**)&VTh,  g_VTh);
    cudaGetSymbolAddress((void**)&P,    g_P);
    cudaGetSymbolAddress((void**)&Ah,   g_Ah);
    cudaGetSymbolAddress((void**)&Wh,   g_Wh);
    cudaGetSymbolAddress((void**)&WoTh, g_WoTh);

    cudaFuncSetAttribute((const void*)bgemm<float>,
                         cudaFuncAttributeMaxDynamicSharedMemorySize, GEMM_SMEM);
    cudaFuncSetAttribute((const void*)bgemm<u16>,
                         cudaFuncAttributeMaxDynamicSharedMemorySize, GEMM_SMEM);

    const long long n4 = (long long)S_LEN * HID / 4;   // 2M float4s
    // 1,2: pack X (two halves so launch #4 lands on the QKV GEMM)
    pack_half_kernel<<<(int)(n4 / 2 / 256), 256>>>(X, Xh, n4 / 2);
    pack_half_kernel<<<(int)(n4 / 2 / 256), 256>>>(
        X + n4 / 2 * 4, Xh + n4 / 2 * 4, n4 / 2);
    // 3: weight transposes (+x64 scale, single fp16 plane)
    transpose_weights_kernel<<<9216, dim3(32, 8)>>>(Wq, Wk, Wv, Wo);
    // 4: merged QKV projection: [4096,2560] = X @ Wqkv   (alpha descales x64)
    bgemm<float><<<dim3(NQKV / 128, S_LEN / 256, 1), 256, GEMM_SMEM>>>(
        Xh, Wh, QKV, HID, HID, HID, NQKV, 0, 0, 0, 1.0f / 64.0f);
    // 5: RoPE -> Qh, Kh
    rope_kernel<<<S_LEN, 128>>>(pos);
    // 6: V^T single plane
    transpose_v_kernel<<<dim3(HD / 32, S_LEN / 32), dim3(32, 8)>>>();
    // 7: scores = (Q K^T)/16 -> fp16 g_P
    bgemm<u16><<<dim3(S_LEN / 128, S_LEN / 256, NH), 256, GEMM_SMEM>>>(
        Qh, Kh, P, HD, HID, HD, S_LEN,
        256LL, 0, (long long)S_LEN * S_LEN, 1.0f / 16.0f);
    // 8: softmax in-place on fp16 g_P
    softmax_kernel<<<S_LEN, 256>>>(mask);
    // 9: A' = P @ V  (fp16 output into Ah)
    bgemm<u16><<<dim3(HD / 128, S_LEN / 256, NH), 256, GEMM_SMEM>>>(
        P, VTh, Ah, S_LEN, S_LEN, S_LEN, HID,
        (long long)S_LEN * S_LEN, 0, 256LL, 1.0f);
    // 10: out = A' @ Wo   (alpha descales x64)
    bgemm<float><<<dim3(HID / 128, S_LEN / 256, 1), 256, GEMM_SMEM>>>(
        Ah, WoTh, out, HID, HID, HID, HID, 0, 0, 0, 1.0f / 64.0f);
}

// round 17
// speedup vs baseline: 1.0835x; 1.0835x over previous
#include <cuda_runtime.h>
#include <cuda_fp16.h>
#include <math.h>
#include <cstdint>

#define S_LEN 4096
#define HID   2048
#define NH    8
#define HD    256
#define NQKV  2560      // 2048 (Q) + 256 (K) + 256 (V)

typedef unsigned short u16;

// ------------------------- device scratch (no allocs allowed) ---------------
__device__ float g_QKV[(size_t)S_LEN * NQKV];        // 40 MB fp32 proj out

__device__ u16 g_Xh  [(size_t)S_LEN * HID];          // fp16 single planes
__device__ u16 g_Qh  [(size_t)S_LEN * HID];
__device__ u16 g_P   [(size_t)NH * S_LEN * S_LEN];   // 268 MB fp16 scores -> P in place
__device__ u16 g_Ah  [(size_t)S_LEN * HID];
__device__ u16 g_Kh  [(size_t)S_LEN * HD];
__device__ u16 g_VTh [(size_t)HD * S_LEN];
__device__ u16 g_Wh  [(size_t)NQKV * HID];           // concat Wq|Wk|Wv transposed, x64
__device__ u16 g_WoTh[(size_t)HID * HID];            // Wo transposed, x64

// ------------------------- helpers ------------------------------------------
__device__ __forceinline__ u16 to_h(float x) {
    return __half_as_ushort(__float2half_rn(x));
}
__device__ __forceinline__ uint32_t smem_u32(const void* p) {
    uint32_t a;
    asm("{ .reg .u64 t; cvta.to.shared.u64 t, %1; cvt.u32.u64 %0, t; }"
        : "=r"(a) : "l"(p));
    return a;
}
__device__ __forceinline__ void cpa16(uint32_t dst, const void* src) {
    asm volatile("cp.async.cg.shared.global [%0], [%1], 16;" :: "r"(dst), "l"(src));
}
__device__ __forceinline__ void cpa_commit() {
    asm volatile("cp.async.commit_group;");
}

#define LDSM4(r, a)                                                            \
    asm volatile("ldmatrix.sync.aligned.m8n8.x4.shared.b16 {%0,%1,%2,%3}, [%4];" \
        : "=r"((r)[0]), "=r"((r)[1]), "=r"((r)[2]), "=r"((r)[3]) : "r"(a))

#define MMA_F16(acc, a, b)                                                     \
    asm volatile(                                                              \
        "mma.sync.aligned.m16n8k16.row.col.f32.f16.f16.f32 "                   \
        "{%0,%1,%2,%3},{%4,%5,%6,%7},{%8,%9},{%0,%1,%2,%3};"                   \
        : "+f"((acc)[0]), "+f"((acc)[1]), "+f"((acc)[2]), "+f"((acc)[3])       \
        : "r"((a)[0]), "r"((a)[1]), "r"((a)[2]), "r"((a)[3]),                  \
          "r"((b)[0]), "r"((b)[1]))

// epilogue store overloads
__device__ __forceinline__ void store2(float* C, long long idx, float a, float b) {
    *(float2*)(C + idx) = make_float2(a, b);
}
__device__ __forceinline__ void store2(u16* C, long long idx, float a, float b) {
    *(__half2*)(C + idx) = __floats2half2_rn(a, b);
}

// ---------------------------------------------------------------------------
// fp16 single-pass GEMM (NT): C[m,n] = alpha * sum_k A[m,k]*B[n,k]
// CTA 128x128 tile, 128 threads / 4 warps (2x2 grid of 64x64 warp tiles),
// 2 CTAs/SM, K-chunk 64, 3 SMEM buffers / 2 in-flight cp.async groups,
// one __syncthreads per chunk.
// NEW (R17): register double-buffered fragments — LDSM for ks+1 issued
// before the 32 MMAs of ks, so crossbar and tensor pipes overlap instead of
// serializing per ks phase.
// SMEM rows: 64 u16 = 128 B, swizzle g' = g ^ (row & 7).
// K multiple of 64 (call sites: 2048 / 256 / 4096 / 2048).
// ---------------------------------------------------------------------------
#define PLANE_B  (128 * 128)            // 16384 B per plane tile
#define STAGE_B  (2 * PLANE_B)          // 32768 B
#define GEMM_SMEM (3 * STAGE_B)         // 98304 B

template <typename OT>
__global__ void __launch_bounds__(128, 2) bgemm(
    const u16* __restrict__ A, const u16* __restrict__ B,
    OT* __restrict__ C,
    int K, int lda, int ldb, int ldc,
    long long sA, long long sB, long long sC, float alpha)
{
    extern __shared__ u16 smraw[];
    const uint32_t smb = smem_u32(smraw);

    const int tid  = threadIdx.x;
    const int wid  = tid >> 5;
    const int lane = tid & 31;
    const int g    = lane >> 2;
    const int tg   = lane & 3;
    const int wm   = (wid >> 1) * 64;   // 2x2 warp grid
    const int wn   = (wid & 1) * 64;

    const int z  = blockIdx.z;
    const int m0 = blockIdx.y * 128;
    const int n0 = blockIdx.x * 128;
    const u16* gA = A + (long long)z * sA + (long long)m0 * lda;
    const u16* gB = B + (long long)z * sB + (long long)n0 * ldb;
    C += (long long)z * sC;

    const int gi    = tid & 7;          // 16B granule within 128B row
    const int rbase = tid >> 3;         // 0..15

    auto issue = [&](int c) {
        const uint32_t sbase = smb + (uint32_t)(c % 3) * STAGE_B;
        const int k0 = c << 6;
#pragma unroll
        for (int t = 0; t < 16; t++) {
            const int p   = t >> 3;                  // plane: 0=A, 1=B
            const int row = ((t & 7) << 4) + rbase;  // 0..127
            const int gs  = gi ^ (row & 7);
            const u16* src = p ? gB : gA;
            const int ld   = p ? ldb : lda;
            cpa16(sbase + (uint32_t)(p * PLANE_B + row * 128 + (gs << 4)),
                  src + (long long)row * ld + k0 + gi * 8);
        }
        cpa_commit();
    };

    float acc[4][8][4];
#pragma unroll
    for (int i = 0; i < 4; i++)
#pragma unroll
        for (int j = 0; j < 8; j++)
#pragma unroll
            for (int r = 0; r < 4; r++) acc[i][j][r] = 0.0f;

    // per-lane ldmatrix base offsets; full offset = base ^ (ks << 5)
    const int l8 = lane & 7;
    const int lt = lane >> 3;
    const int rA = ((lt & 1) << 3) + l8;
    const int gA4 = lt >> 1;
    const int rB = ((lt >> 1) << 3) + l8;
    const int gB4 = lt & 1;

    uint32_t baseA[4], baseB[4];
#pragma unroll
    for (int tm = 0; tm < 4; tm++) {
        const int R = wm + tm * 16 + rA;
        const int s = R & 7;
        baseA[tm] = (uint32_t)(R * 128 + ((gA4 ^ (s & 1)) << 4) + ((s & 6) << 4));
    }
#pragma unroll
    for (int j = 0; j < 4; j++) {
        const int R = wn + j * 16 + rB;
        const int s = R & 7;
        baseB[j] = (uint32_t)(R * 128 + ((gB4 ^ (s & 1)) << 4) + ((s & 6) << 4));
    }

    const int nc = K >> 6;
    issue(0);
    issue(1);

    uint32_t af[2][4][4], bf[2][8][2];

    for (int c = 0; c < nc; c++) {
        if (c < nc - 1) asm volatile("cp.async.wait_group 1;");
        else            asm volatile("cp.async.wait_group 0;");
        __syncthreads();
        if (c + 2 < nc) issue(c + 2);

        const uint32_t st  = smb + (uint32_t)(c % 3) * STAGE_B;
        const uint32_t aPl = st;
        const uint32_t bPl = st + PLANE_B;

        // prime fragments for ks = 0
        {
            LDSM4(af[0][0], aPl + (baseA[0]));
            LDSM4(af[0][1], aPl + (baseA[1]));
            LDSM4(af[0][2], aPl + (baseA[2]));
            LDSM4(af[0][3], aPl + (baseA[3]));
#pragma unroll
            for (int j = 0; j < 4; j++) {
                uint32_t r[4];
                LDSM4(r, bPl + (baseB[j]));
                bf[0][2 * j][0] = r[0]; bf[0][2 * j][1] = r[1];
                bf[0][2 * j + 1][0] = r[2]; bf[0][2 * j + 1][1] = r[3];
            }
        }

#pragma unroll
        for (int ks = 0; ks < 4; ks++) {
            const int cur = ks & 1;
            const int nxt = cur ^ 1;
            // prefetch fragments for ks+1 BEFORE this step's MMAs
            if (ks < 3) {
                const uint32_t kx = (uint32_t)((ks + 1) << 5);
                LDSM4(af[nxt][0], aPl + (baseA[0] ^ kx));
                LDSM4(af[nxt][1], aPl + (baseA[1] ^ kx));
                LDSM4(af[nxt][2], aPl + (baseA[2] ^ kx));
                LDSM4(af[nxt][3], aPl + (baseA[3] ^ kx));
#pragma unroll
                for (int j = 0; j < 4; j++) {
                    uint32_t r[4];
                    LDSM4(r, bPl + (baseB[j] ^ kx));
                    bf[nxt][2 * j][0] = r[0]; bf[nxt][2 * j][1] = r[1];
                    bf[nxt][2 * j + 1][0] = r[2]; bf[nxt][2 * j + 1][1] = r[3];
                }
            }
#pragma unroll
            for (int tm = 0; tm < 4; tm++)
#pragma unroll
                for (int tn = 0; tn < 8; tn++)
                    MMA_F16(acc[tm][tn], af[cur][tm], bf[cur][tn]);
        }
    }

    // epilogue
#pragma unroll
    for (int tm = 0; tm < 4; tm++) {
        const int row = m0 + wm + tm * 16 + g;
#pragma unroll
        for (int tn = 0; tn < 8; tn++) {
            const int col = n0 + wn + tn * 8 + 2 * tg;
            store2(C, (long long)row * ldc + col,
                   acc[tm][tn][0] * alpha, acc[tm][tn][1] * alpha);
            store2(C, (long long)(row + 8) * ldc + col,
                   acc[tm][tn][2] * alpha, acc[tm][tn][3] * alpha);
        }
    }
}

// ---------------------------------------------------------------------------
// fp32 -> fp16 single-plane pack
// ---------------------------------------------------------------------------
__global__ void __launch_bounds__(256) pack_half_kernel(
    const float* __restrict__ in, u16* __restrict__ out, long long n4)
{
    const long long i = (long long)blockIdx.x * 256 + threadIdx.x;
    if (i >= n4) return;
    const float4 v = ((const float4*)in)[i];
    ushort4 o;
    o.x = to_h(v.x); o.y = to_h(v.y); o.z = to_h(v.z); o.w = to_h(v.w);
    ((ushort4*)out)[i] = o;
}

// ---------------------------------------------------------------------------
// Weight transpose + x64 scale -> single fp16 plane.
// ---------------------------------------------------------------------------
__global__ void __launch_bounds__(256) transpose_weights_kernel(
    const float* __restrict__ Wq, const float* __restrict__ Wk,
    const float* __restrict__ Wv, const float* __restrict__ Wo)
{
    __shared__ float tile[32][33];
    const int b = blockIdx.x;
    const int x = threadIdx.x;
    const int y = threadIdx.y;

    const float* src; int scol, sC, n0, k0;
    u16* oh;
    if (b < 5120) {
        const int bx = b % 80, by = b / 80;
        n0 = bx * 32; k0 = by * 32;
        if (n0 < 2048)      { src = Wq; scol = n0;        sC = 2048; }
        else if (n0 < 2304) { src = Wk; scol = n0 - 2048; sC = 256; }
        else                { src = Wv; scol = n0 - 2304; sC = 256; }
        oh = g_Wh;
    } else {
        const int bb = b - 5120;
        const int bx = bb % 64, by = bb / 64;
        n0 = bx * 32; k0 = by * 32;
        src = Wo; scol = n0; sC = 2048;
        oh = g_WoTh;
    }
#pragma unroll
    for (int i = 0; i < 32; i += 8)
        tile[y + i][x] = src[(long long)(k0 + y + i) * sC + scol + x];
    __syncthreads();
#pragma unroll
    for (int i = 0; i < 32; i += 8)
        oh[(long long)(n0 + y + i) * HID + k0 + x] = to_h(tile[x][y + i] * 64.0f);
}

// ---------------------------------------------------------------------------
// RoPE: g_QKV -> Qh, Kh single fp16 planes
// ---------------------------------------------------------------------------
__global__ void rope_kernel(const int* __restrict__ pos_ids)
{
    const int s = blockIdx.x;
    const int j = threadIdx.x;           // 0..127
    const float p = (float)pos_ids[s];
    const float inv = expf(-((float)j * (1.0f / 128.0f)) * logf(10000.0f));
    const float ang = p * inv;
    const float c  = cosf(ang);
    const float sn = sinf(ang);

    const float* row = g_QKV + (size_t)s * NQKV;
#pragma unroll
    for (int h = 0; h < NH; h++) {
        const float x1 = row[h * HD + j];
        const float x2 = row[h * HD + j + 128];
        const size_t o = (size_t)s * HID + h * HD;
        g_Qh[o + j]       = to_h(x1 * c - x2 * sn);
        g_Qh[o + j + 128] = to_h(x2 * c + x1 * sn);
    }
    {
        const float x1 = row[2048 + j];
        const float x2 = row[2048 + j + 128];
        const size_t o = (size_t)s * HD;
        g_Kh[o + j]       = to_h(x1 * c - x2 * sn);
        g_Kh[o + j + 128] = to_h(x2 * c + x1 * sn);
    }
}

// ---------------------------------------------------------------------------
// V transpose: g_QKV cols [2304,2560) -> VT single fp16 plane [256, 4096]
// ---------------------------------------------------------------------------
__global__ void __launch_bounds__(256) transpose_v_kernel()
{
    __shared__ float tile[32][33];
    const int c0 = blockIdx.x * 32;    // d
    const int r0 = blockIdx.y * 32;    // s
    const int x = threadIdx.x;
    const int y = threadIdx.y;
#pragma unroll
    for (int i = 0; i < 32; i += 8)
        tile[y + i][x] = g_QKV[(size_t)(r0 + y + i) * NQKV + 2304 + c0 + x];
    __syncthreads();
#pragma unroll
    for (int i = 0; i < 32; i += 8)
        g_VTh[(size_t)(c0 + y + i) * S_LEN + r0 + x] = to_h(tile[x][y + i]);
}

// ---------------------------------------------------------------------------
// Softmax in-place on fp16 scores (g_P): one block per q row, all 8 heads.
// Vectorized contiguous loads; warp-shuffle reductions.
// ---------------------------------------------------------------------------
__device__ __forceinline__ float block_reduce(float x, float* red, int tid, bool ismax)
{
#pragma unroll
    for (int o = 16; o > 0; o >>= 1) {
        const float y = __shfl_xor_sync(0xFFFFFFFFu, x, o);
        x = ismax ? fmaxf(x, y) : (x + y);
    }
    if ((tid & 31) == 0) red[tid >> 5] = x;
    __syncthreads();
    if (tid < 8) {
        float y = red[tid];
#pragma unroll
        for (int o = 4; o > 0; o >>= 1) {
            const float z = __shfl_xor_sync(0xFFu, y, o);
            y = ismax ? fmaxf(y, z) : (y + z);
        }
        red[tid] = y;
    }
    __syncthreads();
    const float r = red[0];
    __syncthreads();   // allow red reuse
    return r;
}

__global__ void __launch_bounds__(256) softmax_kernel(const float* __restrict__ mask)
{
    const int q = blockIdx.x;
    const int tid = threadIdx.x;
    __shared__ float msk[S_LEN];
    __shared__ float red[8];

    {
        const float4* m4 = (const float4*)(mask + (size_t)q * S_LEN);
        float4* s4 = (float4*)msk;
#pragma unroll
        for (int i = 0; i < 4; i++)
            s4[tid + i * 256] = m4[tid + i * 256];
    }
    __syncthreads();

    const int col0 = tid * 16;
    for (int h = 0; h < NH; h++) {
        u16* __restrict__ row = g_P + ((size_t)h * S_LEN + q) * S_LEN;

        float v[16];
        {
            const uint4 w0 = *(const uint4*)(row + col0);
            const uint4 w1 = *(const uint4*)(row + col0 + 8);
            const uint32_t ws[8] = {w0.x, w0.y, w0.z, w0.w, w1.x, w1.y, w1.z, w1.w};
#pragma unroll
            for (int i = 0; i < 8; i++) {
                const float2 f = __half22float2(*(const __half2*)&ws[i]);
                v[2 * i]     = f.x + msk[col0 + 2 * i];
                v[2 * i + 1] = f.y + msk[col0 + 2 * i + 1];
            }
        }
        float m = v[0];
#pragma unroll
        for (int i = 1; i < 16; i++) m = fmaxf(m, v[i]);
        m = block_reduce(m, red, tid, true);

        float sum = 0.0f;
#pragma unroll
        for (int i = 0; i < 16; i++) {
            v[i] = __expf(v[i] - m);
            sum += v[i];
        }
        sum = block_reduce(sum, red, tid, false);
        const float inv = 1.0f / sum;

        uint4 o0, o1;
#pragma unroll
        for (int i = 0; i < 8; i++) {
            const __half2 hh = __floats2half2_rn(v[2 * i] * inv, v[2 * i + 1] * inv);
            if (i < 4) ((uint32_t*)&o0)[i] = *(const uint32_t*)&hh;
            else       ((uint32_t*)&o1)[i - 4] = *(const uint32_t*)&hh;
        }
        *(uint4*)(row + col0)     = o0;
        *(uint4*)(row + col0 + 8) = o1;
    }
}

// ---------------------------------------------------------------------------
// Launch.  #4 (ncu capture slot) = merged QKV projection GEMM.
// ---------------------------------------------------------------------------
extern "C" void kernel_launch(void* const* d_in, const int* in_sizes, int n_in,
                              void* d_out, int out_size)
{
    const float* X    = (const float*)d_in[0];
    const float* mask = (const float*)d_in[1];
    const int*   pos  = (const int*)d_in[2];
    const float* Wq   = (const float*)d_in[3];
    const float* Wk   = (const float*)d_in[4];
    const float* Wv   = (const float*)d_in[5];
    const float* Wo   = (const float*)d_in[6];
    float* out = (float*)d_out;

    float* QKV;
    u16 *Xh, *Qh, *Kh, *VTh, *P, *Ah, *Wh, *WoTh;
    cudaGetSymbolAddress((void**)&QKV,  g_QKV);
    cudaGetSymbolAddress((void**)&Xh,   g_Xh);
    cudaGetSymbolAddress((void**)&Qh,   g_Qh);
    cudaGetSymbolAddress((void**)&Kh,   g_Kh);
    cudaGetSymbolAddress((void**)&VTh,  g_VTh);
    cudaGetSymbolAddress((void**)&P,    g_P);
    cudaGetSymbolAddress((void**)&Ah,   g_Ah);
    cudaGetSymbolAddress((void**)&Wh,   g_Wh);
    cudaGetSymbolAddress((void**)&WoTh, g_WoTh);

    cudaFuncSetAttribute((const void*)bgemm<float>,
                         cudaFuncAttributeMaxDynamicSharedMemorySize, GEMM_SMEM);
    cudaFuncSetAttribute((const void*)bgemm<u16>,
                         cudaFuncAttributeMaxDynamicSharedMemorySize, GEMM_SMEM);

    const long long n4 = (long long)S_LEN * HID / 4;   // 2M float4s
    // 1,2: pack X (two halves so launch #4 lands on the QKV GEMM)
    pack_half_kernel<<<(int)(n4 / 2 / 256), 256>>>(X, Xh, n4 / 2);
    pack_half_kernel<<<(int)(n4 / 2 / 256), 256>>>(
        X + n4 / 2 * 4, Xh + n4 / 2 * 4, n4 / 2);
    // 3: weight transposes (+x64 scale, single fp16 plane)
    transpose_weights_kernel<<<9216, dim3(32, 8)>>>(Wq, Wk, Wv, Wo);
    // 4: merged QKV projection: [4096,2560] = X @ Wqkv   (alpha descales x64)
    bgemm<float><<<dim3(NQKV / 128, S_LEN / 128, 1), 128, GEMM_SMEM>>>(
        Xh, Wh, QKV, HID, HID, HID, NQKV, 0, 0, 0, 1.0f / 64.0f);
    // 5: RoPE -> Qh, Kh
    rope_kernel<<<S_LEN, 128>>>(pos);
    // 6: V^T single plane
    transpose_v_kernel<<<dim3(HD / 32, S_LEN / 32), dim3(32, 8)>>>();
    // 7: scores = (Q K^T)/16 -> fp16 g_P
    bgemm<u16><<<dim3(S_LEN / 128, S_LEN / 128, NH), 128, GEMM_SMEM>>>(
        Qh, Kh, P, HD, HID, HD, S_LEN,
        256LL, 0, (long long)S_LEN * S_LEN, 1.0f / 16.0f);
    // 8: softmax in-place on fp16 g_P
    softmax_kernel<<<S_LEN, 256>>>(mask);
    // 9: A' = P @ V  (fp16 output into Ah)
    bgemm<u16><<<dim3(HD / 128, S_LEN / 128, NH), 128, GEMM_SMEM>>>(
        P, VTh, Ah, S_LEN, S_LEN, S_LEN, HID,
        (long long)S_LEN * S_LEN, 0, 256LL, 1.0f);
    // 10: out = A' @ Wo   (alpha descales x64)
    bgemm<float><<<dim3(HID / 128, S_LEN / 128, 1), 128, GEMM_SMEM>>>(
        Ah, WoTh, out, HID, HID, HID, HID, 0, 0, 0, 1.0f / 64.0f);
}